// round 4
// baseline (speedup 1.0000x reference)
#include <cuda_runtime.h>

// TTN_Conv_2by2to1: out[n,p,o,x,y] = sum_{c,m} patch[n,c,m,x,y] * W[c,p,x,y,m,o] + bias[p,x,y,o]
// patch[n,c,(i,j,k,l),x,y] = a_i*b_j*c_k*d_l from the 2x2 corners of x.
//
// One block per (x,y). Per c: stage the weight slice to smem (transposed,
// padded), build 16-entry ab/cd tables per n, materialize patch[m][n] in
// smem (each value reused 48x), then an FMA-pipe-bound accumulation using
// Blackwell packed fp32x2 FMAs (fma.rn.f32x2 = 2x scalar FFMA throughput).

#define NUM   128
#define CIN   3
#define COUT  8
#define NX    31
#define NY    31
#define NXY   (NX*NY)          // 961
#define DIN   4
#define DOUT  6
#define MDIM  256              // din^4
#define SX    32
#define SY    32

// shared memory layout (float offsets)
#define PATCH_OFF 0
#define PATCH_SZ  (MDIM*NUM)            // 32768 floats (128 KB)
#define W_ROW     258                   // 256 + pad
#define W_OFF     (PATCH_OFF+PATCH_SZ)  // 32768
#define W_SZ      (COUT*DOUT*W_ROW)     // 12384 floats (49.5 KB)
#define AB_ROW    17                    // 16 + pad (odd stride -> conflict-free)
#define AB_OFF    (W_OFF+W_SZ)          // 45152
#define AB_SZ     (NUM*AB_ROW)          // 2176
#define CD_OFF    (AB_OFF+AB_SZ)        // 47328
#define CD_SZ     AB_SZ
#define SMEM_FLOATS (CD_OFF+CD_SZ)      // 49504
#define SMEM_BYTES  (SMEM_FLOATS*4)     // 198016 B

__device__ __forceinline__ unsigned long long pack2(float lo, float hi) {
    unsigned long long r;
    asm("mov.b64 %0, {%1,%2};" : "=l"(r) : "f"(lo), "f"(hi));
    return r;
}
__device__ __forceinline__ void unpack2(unsigned long long v, float& lo, float& hi) {
    asm("mov.b64 {%0,%1}, %2;" : "=f"(lo), "=f"(hi) : "l"(v));
}
// packed dual fp32 FMA: d = a*b + d  (two fp32 lanes per 64-bit register pair)
__device__ __forceinline__ void ffma2(unsigned long long& d,
                                      unsigned long long a,
                                      unsigned long long b) {
    asm("fma.rn.f32x2 %0, %1, %2, %0;" : "+l"(d) : "l"(a), "l"(b));
}

__global__ __launch_bounds__(256, 1)
void ttn_kernel(const float* __restrict__ x,
                const float* __restrict__ w,
                const float* __restrict__ bias,
                float* __restrict__ out)
{
    extern __shared__ float smem[];
    float* patch_s = smem + PATCH_OFF;   // [m][n], n fastest (128 per row)
    float* w_s     = smem + W_OFF;       // [(p*6+o)][m], row stride W_ROW
    float* ab_s    = smem + AB_OFF;      // [n][ij], row stride AB_ROW
    float* cd_s    = smem + CD_OFF;      // [n][kl]

    const int tid = threadIdx.x;
    const int xy  = blockIdx.x;
    const int Xi  = xy / NY;
    const int Yi  = xy - Xi * NY;

    // thread tile: 8 n (4 f32x2 pairs) x 3 o; p/o0 from thread id.
    // lanes sharing g read the same w address (warp broadcast); ng covers
    // the patch row contiguously -> conflict-free LDS.128.
    const int ng = tid & 15;        // n-group: n = ng*8 .. ng*8+7
    const int g  = tid >> 4;        // 0..15
    const int p  = g >> 1;          // 0..7
    const int o0 = (g & 1) * 3;     // 0 or 3

    unsigned long long acc[3][4];
    #pragma unroll
    for (int oi = 0; oi < 3; ++oi)
        #pragma unroll
        for (int q = 0; q < 4; ++q)
            acc[oi][q] = pack2(0.0f, 0.0f);

    const int corner = Xi * SY + Yi;   // (X,Y) offset within one (n,c,i) plane

    for (int c = 0; c < CIN; ++c) {
        // ---- stage weight slice for this (c, xy): transpose to [po][m] ----
        {
            const float* wc = w + ((size_t)(c * COUT) * NXY + xy) * (MDIM * DOUT);
            const size_t pstride = (size_t)NXY * (MDIM * DOUT);
            for (int idx = tid; idx < (COUT * MDIM * DOUT) / 4; idx += 256) {
                int pp = idx / (MDIM * DOUT / 4);        // /384
                int r  = idx - pp * (MDIM * DOUT / 4);
                float4 v = __ldg(reinterpret_cast<const float4*>(wc + pp * pstride) + r);
                int t = r * 4;                            // element index = m*6+o
                float vv[4] = {v.x, v.y, v.z, v.w};
                #pragma unroll
                for (int e = 0; e < 4; ++e) {
                    int tt = t + e;
                    int mI = tt / 6;
                    int oI = tt - mI * 6;
                    w_s[(pp * DOUT + oI) * W_ROW + mI] = vv[e];
                }
            }
        }
        // ---- ab/cd outer-product tables (threads 0..127, one n each) ----
        if (tid < NUM) {
            const float* xp = x + ((size_t)(tid * CIN + c) * DIN) * (SX * SY) + corner;
            float av[4], bv[4], cv[4], dv[4];
            #pragma unroll
            for (int i = 0; i < 4; ++i) {
                av[i] = __ldg(xp + i * (SX * SY));            // (X  , Y  )
                bv[i] = __ldg(xp + i * (SX * SY) + SY);       // (X+1, Y  )
                cv[i] = __ldg(xp + i * (SX * SY) + 1);        // (X  , Y+1)
                dv[i] = __ldg(xp + i * (SX * SY) + SY + 1);   // (X+1, Y+1)
            }
            #pragma unroll
            for (int i = 0; i < 4; ++i)
                #pragma unroll
                for (int j = 0; j < 4; ++j) {
                    ab_s[tid * AB_ROW + i * 4 + j] = av[i] * bv[j];
                    cd_s[tid * AB_ROW + i * 4 + j] = cv[i] * dv[j];
                }
        }
        __syncthreads();

        // ---- materialize patch[m][n]: each value reused 48x below ----
        #pragma unroll 4
        for (int idx = tid; idx < MDIM * NUM; idx += 256) {
            int n = idx & (NUM - 1);
            int m = idx >> 7;
            patch_s[idx] = ab_s[n * AB_ROW + (m >> 4)] * cd_s[n * AB_ROW + (m & 15)];
        }
        __syncthreads();

        // ---- main accumulation, m in pairs: FMA-pipe bound ----
        const float* wrow = w_s + (p * DOUT + o0) * W_ROW;
        const float* prow = patch_s + (ng << 3);
        #pragma unroll 4
        for (int m = 0; m < MDIM; m += 2) {
            const ulonglong2* pr0 =
                reinterpret_cast<const ulonglong2*>(prow + (m << 7));
            const ulonglong2* pr1 =
                reinterpret_cast<const ulonglong2*>(prow + ((m + 1) << 7));
            ulonglong2 a0 = pr0[0];          // m   : n pairs (0,1),(2,3)
            ulonglong2 a1 = pr0[1];          // m   : n pairs (4,5),(6,7)
            ulonglong2 b0 = pr1[0];          // m+1
            ulonglong2 b1 = pr1[1];
            #pragma unroll
            for (int oi = 0; oi < 3; ++oi) {
                // LDS.64: weights for (m, m+1), warp broadcast
                float2 wv = *reinterpret_cast<const float2*>(wrow + oi * W_ROW + m);
                unsigned long long w0 = pack2(wv.x, wv.x);
                unsigned long long w1 = pack2(wv.y, wv.y);
                ffma2(acc[oi][0], a0.x, w0);
                ffma2(acc[oi][1], a0.y, w0);
                ffma2(acc[oi][2], a1.x, w0);
                ffma2(acc[oi][3], a1.y, w0);
                ffma2(acc[oi][0], b0.x, w1);
                ffma2(acc[oi][1], b0.y, w1);
                ffma2(acc[oi][2], b1.x, w1);
                ffma2(acc[oi][3], b1.y, w1);
            }
        }
        __syncthreads();   // protect smem before next c's staging
    }

    // ---- epilogue: bias + store (out[n][p][o][xy]) ----
    const int n0 = ng * 8;
    #pragma unroll
    for (int oi = 0; oi < 3; ++oi) {
        const int o = o0 + oi;
        const float bv = __ldg(bias + ((size_t)p * NXY + xy) * DOUT + o);
        float* ob = out + (size_t)p * (DOUT * NXY) + (size_t)o * NXY + xy;
        #pragma unroll
        for (int q = 0; q < 4; ++q) {
            float lo, hi;
            unpack2(acc[oi][q], lo, hi);
            ob[(size_t)(n0 + 2 * q)     * (COUT * DOUT * NXY)] = lo + bv;
            ob[(size_t)(n0 + 2 * q + 1) * (COUT * DOUT * NXY)] = hi + bv;
        }
    }
}

extern "C" void kernel_launch(void* const* d_in, const int* in_sizes, int n_in,
                              void* d_out, int out_size)
{
    const float* x    = (const float*)d_in[0];
    const float* w    = (const float*)d_in[1];
    const float* bias = (const float*)d_in[2];
    float* out = (float*)d_out;

    cudaFuncSetAttribute(ttn_kernel,
                         cudaFuncAttributeMaxDynamicSharedMemorySize, SMEM_BYTES);
    ttn_kernel<<<NXY, 256, SMEM_BYTES>>>(x, w, bias, out);
}

// round 5
// speedup vs baseline: 2.2728x; 2.2728x over previous
#include <cuda_runtime.h>

// TTN_Conv_2by2to1: out[n,p,o,x,y] = sum_{c,m} patch[n,c,m,x,y] * W[c,p,x,y,m,o] + bias[p,x,y,o]
// patch m=(i,j,k,l): a_i*b_j*c_k*d_l from the 2x2 corners of x.
//
// One block per (x,y), 256 threads, warp = one p, thread tile 4n x 6o.
// patch is NOT materialized: ab_t[ij][n], cd_t[kl][n] tables (8 KB each) and
// on-the-fly packed fp32x2 multiply. Weights staged transposed [p*6+o][m] and
// read as m-quad LDS.128 broadcasts. 66.8 KB smem -> 2 CTAs/SM (16 warps).

#define NUM   128
#define CIN   3
#define COUT  8
#define NXY   961
#define DOUT  6
#define MDIM  256
#define SX    32
#define SY    32

// smem layout (float offsets)
#define W_ROW  260                    // 256 + pad, 16B-aligned rows (1040 B)
#define W_OFF  0
#define W_SZ   (COUT*DOUT*W_ROW)      // 12480 floats
#define AB_ROW 132                    // 128 + pad, 16B-aligned rows (528 B)
#define AB_OFF W_SZ                   // 12480 (x4 B = 49920, %16==0)
#define AB_SZ  (16*AB_ROW)            // 2112
#define CD_OFF (AB_OFF+AB_SZ)         // 14592
#define SMEM_FLOATS (CD_OFF+AB_SZ)    // 16704
#define SMEM_BYTES  (SMEM_FLOATS*4)   // 66816 B -> 2 CTAs/SM

typedef unsigned long long ull;

__device__ __forceinline__ ull pack2(float lo, float hi) {
    ull r; asm("mov.b64 %0, {%1,%2};" : "=l"(r) : "f"(lo), "f"(hi)); return r;
}
__device__ __forceinline__ void unpack2(ull v, float& lo, float& hi) {
    asm("mov.b64 {%0,%1}, %2;" : "=f"(lo), "=f"(hi) : "l"(v));
}
__device__ __forceinline__ ull fmul2(ull a, ull b) {
    ull r; asm("mul.rn.f32x2 %0, %1, %2;" : "=l"(r) : "l"(a), "l"(b)); return r;
}
__device__ __forceinline__ void ffma2(ull& d, ull a, ull b) {
    asm("fma.rn.f32x2 %0, %1, %2, %0;" : "+l"(d) : "l"(a), "l"(b));
}

__global__ __launch_bounds__(256, 2)
void ttn_kernel(const float* __restrict__ x,
                const float* __restrict__ w,
                const float* __restrict__ bias,
                float* __restrict__ out)
{
    extern __shared__ float smem[];
    float* w_s  = smem + W_OFF;    // [(p*6+o)][m], row stride W_ROW
    float* ab_t = smem + AB_OFF;   // [ij][n], row stride AB_ROW
    float* cd_t = smem + CD_OFF;   // [kl][n]

    const int tid  = threadIdx.x;
    const int xy   = blockIdx.x;
    const int Xi   = xy / 31;
    const int Yi   = xy - Xi * 31;
    const int lane = tid & 31;
    const int p    = tid >> 5;       // warp id = output channel p (0..7)
    const int n0   = lane << 2;      // 4 consecutive n per thread

    ull acc[DOUT][2];
    #pragma unroll
    for (int o = 0; o < DOUT; ++o) { acc[o][0] = 0ULL; acc[o][1] = 0ULL; }

    const int corner = Xi * SY + Yi;

    for (int c = 0; c < CIN; ++c) {
        // ---- stage weight slice for (c, xy): transpose to [p*6+o][m] ----
        {
            const float* wc = w + ((size_t)(c * COUT) * NXY + xy) * (MDIM * DOUT);
            const size_t pstride = (size_t)NXY * (MDIM * DOUT);
            #pragma unroll
            for (int it = 0; it < 12; ++it) {
                int idx = tid + it * 256;                // 3072 float4 total
                int pp  = idx / 384;                     // 384 float4 per p
                int r   = idx - pp * 384;
                float4 v = __ldg(reinterpret_cast<const float4*>(wc + pp * pstride) + r);
                int t = r * 4;                           // element = m*6+o
                float vv[4] = {v.x, v.y, v.z, v.w};
                #pragma unroll
                for (int e = 0; e < 4; ++e) {
                    int tt = t + e;
                    int mI = tt / 6;
                    int oI = tt - mI * 6;
                    w_s[(pp * DOUT + oI) * W_ROW + mI] = vv[e];
                }
            }
        }
        // ---- ab/cd tables, transposed [ij][n] (threads 0..127, one n each) ----
        if (tid < NUM) {
            const float* xp = x + ((size_t)(tid * CIN + c) * 4) * (SX * SY) + corner;
            float av[4], bv[4], cv[4], dv[4];
            #pragma unroll
            for (int i = 0; i < 4; ++i) {
                av[i] = __ldg(xp + i * (SX * SY));            // (X  , Y  )
                bv[i] = __ldg(xp + i * (SX * SY) + SY);       // (X+1, Y  )
                cv[i] = __ldg(xp + i * (SX * SY) + 1);        // (X  , Y+1)
                dv[i] = __ldg(xp + i * (SX * SY) + SY + 1);   // (X+1, Y+1)
            }
            #pragma unroll
            for (int i = 0; i < 4; ++i)
                #pragma unroll
                for (int j = 0; j < 4; ++j) {
                    ab_t[(i * 4 + j) * AB_ROW + tid] = av[i] * bv[j];
                    cd_t[(i * 4 + j) * AB_ROW + tid] = cv[i] * dv[j];
                }
        }
        __syncthreads();

        // ---- main loop: on-the-fly patch, m-quad weights, packed FMAs ----
        const float* wbase = w_s + p * DOUT * W_ROW;
        for (int ij = 0; ij < 16; ++ij) {
            ulonglong2 aV = *reinterpret_cast<const ulonglong2*>(ab_t + ij * AB_ROW + n0);
            const ull a01 = aV.x, a23 = aV.y;       // ab for n0..n0+3
            #pragma unroll
            for (int kl = 0; kl < 16; kl += 4) {
                const int m = (ij << 4) + kl;
                ull p01[4], p23[4];
                #pragma unroll
                for (int q = 0; q < 4; ++q) {
                    ulonglong2 cV = *reinterpret_cast<const ulonglong2*>(
                        cd_t + (kl + q) * AB_ROW + n0);
                    p01[q] = fmul2(a01, cV.x);      // patch(m+q) for n0,n0+1
                    p23[q] = fmul2(a23, cV.y);      // patch(m+q) for n0+2,n0+3
                }
                #pragma unroll
                for (int o = 0; o < DOUT; ++o) {
                    // LDS.128 broadcast: weights w[p][o][m..m+3]
                    float4 wq = *reinterpret_cast<const float4*>(wbase + o * W_ROW + m);
                    float wa[4] = {wq.x, wq.y, wq.z, wq.w};
                    #pragma unroll
                    for (int q = 0; q < 4; ++q) {
                        ull wd = pack2(wa[q], wa[q]);
                        ffma2(acc[o][0], p01[q], wd);
                        ffma2(acc[o][1], p23[q], wd);
                    }
                }
            }
        }
        __syncthreads();   // protect smem before next c's staging
    }

    // ---- epilogue: bias + store out[n][p][o][xy] ----
    #pragma unroll
    for (int o = 0; o < DOUT; ++o) {
        const float bv = __ldg(bias + ((size_t)p * NXY + xy) * DOUT + o);
        float* ob = out + (size_t)p * (DOUT * NXY) + (size_t)o * NXY + xy;
        #pragma unroll
        for (int q = 0; q < 2; ++q) {
            float lo, hi;
            unpack2(acc[o][q], lo, hi);
            ob[(size_t)(n0 + 2 * q)     * (COUT * DOUT * NXY)] = lo + bv;
            ob[(size_t)(n0 + 2 * q + 1) * (COUT * DOUT * NXY)] = hi + bv;
        }
    }
}

extern "C" void kernel_launch(void* const* d_in, const int* in_sizes, int n_in,
                              void* d_out, int out_size)
{
    const float* x    = (const float*)d_in[0];
    const float* w    = (const float*)d_in[1];
    const float* bias = (const float*)d_in[2];
    float* out = (float*)d_out;

    cudaFuncSetAttribute(ttn_kernel,
                         cudaFuncAttributeMaxDynamicSharedMemorySize, SMEM_BYTES);
    ttn_kernel<<<NXY, 256, SMEM_BYTES>>>(x, w, bias, out);
}